// round 1
// baseline (speedup 1.0000x reference)
#include <cuda_runtime.h>
#include <math.h>
#include <float.h>

// ---------------- problem constants ----------------
#define T_TOK 8192      // B*S tokens
#define HD    2048      // hidden
#define ID    1024      // moe intermediate
#define KQ    8         // quantum basis count
#define NE    128       // experts
#define KI    8192      // KQ * ID
#define I2    2048      // 2 * ID (shared expert intermediate)

// ---------------- device scratch (static; no allocations allowed) ----------------
__device__ float g_gate[67108864];   // [T, KI]   gate pre-activation
__device__ float g_up[67108864];     // [T, KI]   up projection
__device__ float g_z[8388608];       // [T, ID]   mixed basis
__device__ float g_sg[16777216];     // [T, I2]   shared gate
__device__ float g_su[16777216];     // [T, I2]   shared up
__device__ float g_h[16777216];      // [T, I2]   shared hidden
__device__ float g_logits[1048576];  // [T, NE]
__device__ float g_wk[65536];        // [T, KQ]   collapsed per-token mixing weights
__device__ float g_mix[1024];        // [NE, KQ]  normalized amplitude mixing

// ---------------- generic 128x128x8 SGEMM, row-major, MODE 0 = store, 1 = accumulate ----------------
template<int MODE>
__global__ __launch_bounds__(256, 2)
void sgemm_k(const float* __restrict__ A, const float* __restrict__ B,
             float* __restrict__ C, int M, int N, int Kd)
{
    __shared__ float As[8][128];
    __shared__ float Bs[8][128];
    const int tid  = threadIdx.x;
    const int tx   = tid & 15;
    const int ty   = tid >> 4;
    const int row0 = blockIdx.y * 128;
    const int col0 = blockIdx.x * 128;

    const int aRow = tid >> 1;
    const int aCol = (tid & 1) << 2;
    const int bRow = tid >> 5;
    const int bCol = (tid & 31) << 2;

    const float* Ap = A + (size_t)(row0 + aRow) * Kd + aCol;
    const float* Bp = B + (size_t)bRow * N + col0 + bCol;

    float acc[8][8];
#pragma unroll
    for (int i = 0; i < 8; i++)
#pragma unroll
        for (int j = 0; j < 8; j++) acc[i][j] = 0.f;

    for (int k0 = 0; k0 < Kd; k0 += 8) {
        float4 av = *(const float4*)Ap;
        float4 bv = *(const float4*)Bp;
        As[aCol + 0][aRow] = av.x;
        As[aCol + 1][aRow] = av.y;
        As[aCol + 2][aRow] = av.z;
        As[aCol + 3][aRow] = av.w;
        *(float4*)&Bs[bRow][bCol] = bv;
        __syncthreads();
#pragma unroll
        for (int kk = 0; kk < 8; kk++) {
            float a[8], b[8];
            *(float4*)&a[0] = *(const float4*)&As[kk][ty * 8];
            *(float4*)&a[4] = *(const float4*)&As[kk][ty * 8 + 4];
            *(float4*)&b[0] = *(const float4*)&Bs[kk][tx * 8];
            *(float4*)&b[4] = *(const float4*)&Bs[kk][tx * 8 + 4];
#pragma unroll
            for (int i = 0; i < 8; i++)
#pragma unroll
                for (int j = 0; j < 8; j++)
                    acc[i][j] = fmaf(a[i], b[j], acc[i][j]);
        }
        __syncthreads();
        Ap += 8;
        Bp += (size_t)8 * N;
    }

#pragma unroll
    for (int i = 0; i < 8; i++) {
        float* Cp = C + (size_t)(row0 + ty * 8 + i) * N + col0 + tx * 8;
        if (MODE == 0) {
            *(float4*)Cp       = make_float4(acc[i][0], acc[i][1], acc[i][2], acc[i][3]);
            *(float4*)(Cp + 4) = make_float4(acc[i][4], acc[i][5], acc[i][6], acc[i][7]);
        } else {
            float4 c0 = *(float4*)Cp;
            float4 c1 = *(float4*)(Cp + 4);
            c0.x += acc[i][0]; c0.y += acc[i][1]; c0.z += acc[i][2]; c0.w += acc[i][3];
            c1.x += acc[i][4]; c1.y += acc[i][5]; c1.z += acc[i][6]; c1.w += acc[i][7];
            *(float4*)Cp       = c0;
            *(float4*)(Cp + 4) = c1;
        }
    }
}

// ---------------- amplitudes -> normalized mix [NE, KQ] ----------------
__global__ void mix_kernel(const float* __restrict__ amp)
{
    int e = threadIdx.x;
    if (e >= NE) return;
    float p[KQ];
    float s = 0.f;
#pragma unroll
    for (int k = 0; k < KQ; k++) {
        float a0 = amp[(e * KQ + k) * 2 + 0];
        float a1 = amp[(e * KQ + k) * 2 + 1];
        p[k] = a0 * a0 + a1 * a1;
        s += p[k];
    }
    float inv = 1.f / (s + 1e-8f);
#pragma unroll
    for (int k = 0; k < KQ; k++) g_mix[e * KQ + k] = p[k] * inv;
}

// ---------------- softmax + top-4 + collapse to wk[t,k] (one warp per token) ----------------
__global__ void topk_kernel(const float* __restrict__ expert_scale)
{
    int lane = threadIdx.x & 31;
    int warp = threadIdx.x >> 5;
    int t = blockIdx.x * 8 + warp;
    const float* lrow = g_logits + (size_t)t * NE;

    float v[4];
#pragma unroll
    for (int j = 0; j < 4; j++) v[j] = lrow[lane + 32 * j];

    float m = fmaxf(fmaxf(v[0], v[1]), fmaxf(v[2], v[3]));
#pragma unroll
    for (int o = 16; o; o >>= 1) m = fmaxf(m, __shfl_xor_sync(0xffffffffu, m, o));

    float D = 0.f;
#pragma unroll
    for (int j = 0; j < 4; j++) D += expf(v[j] - m);
#pragma unroll
    for (int o = 16; o; o >>= 1) D += __shfl_xor_sync(0xffffffffu, D, o);

    float lv[4] = {v[0], v[1], v[2], v[3]};
    float selv[4];
    int   seli[4];
#pragma unroll
    for (int it = 0; it < 4; it++) {
        float bv = -FLT_MAX;
        int   bi = NE;
#pragma unroll
        for (int j = 0; j < 4; j++) {
            int e = lane + 32 * j;
            if (lv[j] > bv) { bv = lv[j]; bi = e; }
        }
#pragma unroll
        for (int o = 16; o; o >>= 1) {
            float ov = __shfl_xor_sync(0xffffffffu, bv, o);
            int   oi = __shfl_xor_sync(0xffffffffu, bi, o);
            if (ov > bv || (ov == bv && oi < bi)) { bv = ov; bi = oi; }
        }
        selv[it] = bv;
        seli[it] = bi;
        if ((bi & 31) == lane) lv[bi >> 5] = -FLT_MAX;
    }

    float ew[4];
    float S = 0.f;
#pragma unroll
    for (int it = 0; it < 4; it++) { ew[it] = expf(selv[it] - m); S += ew[it]; }
    // topk_w = (e/D) / (S/D + EPS) = e / (S + EPS*D)
    float denom = S + 1e-8f * D;

    if (lane < KQ) {
        float acc = 0.f;
#pragma unroll
        for (int it = 0; it < 4; it++)
            acc += (ew[it] / denom) * expert_scale[seli[it]] * g_mix[seli[it] * KQ + lane];
        g_wk[t * KQ + lane] = acc;
    }
}

// ---------------- z[t,i] = sum_k wk[t,k] * silu(gate) * up ----------------
__global__ void moe_mix_kernel()
{
    int t = blockIdx.y;
    int i = blockIdx.x * 256 + threadIdx.x;
    __shared__ float w[KQ];
    if (threadIdx.x < KQ) w[threadIdx.x] = g_wk[t * KQ + threadIdx.x];
    __syncthreads();
    float acc = 0.f;
#pragma unroll
    for (int k = 0; k < KQ; k++) {
        size_t off = (size_t)t * KI + k * ID + i;
        float g = g_gate[off];
        float u = g_up[off];
        acc += w[k] * (g / (1.f + expf(-g))) * u;
    }
    g_z[(size_t)t * ID + i] = acc;
}

// ---------------- shared expert elementwise: h = silu(sg) * su ----------------
__global__ void silu_mul_kernel()
{
    size_t idx = (size_t)blockIdx.x * 256 + threadIdx.x;
    float g = g_sg[idx];
    float u = g_su[idx];
    g_h[idx] = (g / (1.f + expf(-g))) * u;
}

// ---------------- launch ----------------
extern "C" void kernel_launch(void* const* d_in, const int* in_sizes, int n_in,
                              void* d_out, int out_size)
{
    const float* x              = (const float*)d_in[0];
    const float* w_router       = (const float*)d_in[1];
    const float* w_gate         = (const float*)d_in[2];
    const float* w_up           = (const float*)d_in[3];
    const float* w_down         = (const float*)d_in[4];
    const float* amplitudes     = (const float*)d_in[5];
    const float* expert_scale   = (const float*)d_in[6];
    const float* shared_w_gate  = (const float*)d_in[7];
    const float* shared_w_up    = (const float*)d_in[8];
    const float* shared_w_down  = (const float*)d_in[9];
    float* out = (float*)d_out;

    void *pg, *pu, *pz, *psg, *psu, *ph, *plog;
    cudaGetSymbolAddress(&pg,   g_gate);
    cudaGetSymbolAddress(&pu,   g_up);
    cudaGetSymbolAddress(&pz,   g_z);
    cudaGetSymbolAddress(&psg,  g_sg);
    cudaGetSymbolAddress(&psu,  g_su);
    cudaGetSymbolAddress(&ph,   g_h);
    cudaGetSymbolAddress(&plog, g_logits);

    // 1. tiny: normalized mixing weights from amplitudes
    mix_kernel<<<1, 128>>>(amplitudes);

    // 2. router logits: [T,HD] x [HD,NE]
    sgemm_k<0><<<dim3(NE / 128, T_TOK / 128), 256>>>(x, w_router, (float*)plog, T_TOK, NE, HD);

    // 3. softmax + top-4 + collapse TOPK into wk[t,k]
    topk_kernel<<<T_TOK / 8, 256>>>(expert_scale);

    // 4. gate / up projections: [T,HD] x [HD,KI]
    sgemm_k<0><<<dim3(KI / 128, T_TOK / 128), 256>>>(x, w_gate, (float*)pg, T_TOK, KI, HD);
    sgemm_k<0><<<dim3(KI / 128, T_TOK / 128), 256>>>(x, w_up,   (float*)pu, T_TOK, KI, HD);

    // 5. z[t,i] = sum_k wk * silu(gate) * up
    moe_mix_kernel<<<dim3(ID / 256, T_TOK), 256>>>();

    // 6. down projection (TOPK collapsed): out = z @ w_down
    sgemm_k<0><<<dim3(HD / 128, T_TOK / 128), 256>>>((const float*)pz, w_down, out, T_TOK, HD, ID);

    // 7. shared expert
    sgemm_k<0><<<dim3(I2 / 128, T_TOK / 128), 256>>>(x, shared_w_gate, (float*)psg, T_TOK, I2, HD);
    sgemm_k<0><<<dim3(I2 / 128, T_TOK / 128), 256>>>(x, shared_w_up,   (float*)psu, T_TOK, I2, HD);
    silu_mul_kernel<<<(T_TOK * I2) / 256, 256>>>();

    // 8. out += h @ shared_w_down
    sgemm_k<1><<<dim3(HD / 128, T_TOK / 128), 256>>>((const float*)ph, shared_w_down, out, T_TOK, HD, I2);
}

// round 3
// speedup vs baseline: 2.9030x; 2.9030x over previous
#include <cuda_runtime.h>
#include <cuda_bf16.h>
#include <math.h>
#include <float.h>
#include <stdint.h>

// ---------------- problem constants ----------------
#define T_TOK 8192
#define HD    2048
#define ID    1024
#define KQ    8
#define NE    128
#define KI    8192
#define I2    2048

// ---------------- fp32 scratch ----------------
__device__ float g_gate[67108864];   // [T, KI]
__device__ float g_up[67108864];     // [T, KI]
__device__ float g_sg[16777216];     // [T, I2]
__device__ float g_su[16777216];     // [T, I2]
__device__ float g_logits[1048576];  // [T, NE]
__device__ float g_wk[65536];        // [T, KQ]
__device__ float g_mix[1024];        // [NE, KQ]

// ---------------- bf16 hi/lo scratch ----------------
__device__ __nv_bfloat16 g_xh[16777216],  g_xl[16777216];   // x [T,HD]
__device__ __nv_bfloat16 g_wgh[16777216], g_wgl[16777216];  // w_gate [HD,KI]
__device__ __nv_bfloat16 g_wuh[16777216], g_wul[16777216];  // w_up
__device__ __nv_bfloat16 g_wdh[2097152],  g_wdl[2097152];   // w_down [ID,HD]
__device__ __nv_bfloat16 g_sgh[4194304],  g_sgl[4194304];   // shared_w_gate [HD,I2]
__device__ __nv_bfloat16 g_suh[4194304],  g_sul[4194304];   // shared_w_up
__device__ __nv_bfloat16 g_sdh[4194304],  g_sdl[4194304];   // shared_w_down [I2,HD]
__device__ __nv_bfloat16 g_wrh[262144],   g_wrl[262144];    // w_router [HD,NE]
__device__ __nv_bfloat16 g_zh[8388608],   g_zl[8388608];    // z [T,ID]
__device__ __nv_bfloat16 g_hh[16777216],  g_hl[16777216];   // h [T,I2]

// ================= low-level helpers =================
__device__ __forceinline__ uint32_t smem_u32(const void* p) {
    uint32_t a;
    asm("{ .reg .u64 t; cvta.to.shared.u64 t, %1; cvt.u32.u64 %0, t; }" : "=r"(a) : "l"(p));
    return a;
}
__device__ __forceinline__ void cp16(uint32_t dst, const void* src) {
    asm volatile("cp.async.cg.shared.global [%0], [%1], 16;" :: "r"(dst), "l"(src));
}
__device__ __forceinline__ void cp_commit() {
    asm volatile("cp.async.commit_group;" ::: "memory");
}
template<int N> __device__ __forceinline__ void cp_wait() {
    asm volatile("cp.async.wait_group %0;" :: "n"(N) : "memory");
}
__device__ __forceinline__ void ldsm4(uint32_t* r, uint32_t addr) {
    asm volatile("ldmatrix.sync.aligned.m8n8.x4.shared.b16 {%0,%1,%2,%3}, [%4];"
                 : "=r"(r[0]), "=r"(r[1]), "=r"(r[2]), "=r"(r[3]) : "r"(addr));
}
__device__ __forceinline__ void ldsm4t(uint32_t* r, uint32_t addr) {
    asm volatile("ldmatrix.sync.aligned.m8n8.x4.trans.shared.b16 {%0,%1,%2,%3}, [%4];"
                 : "=r"(r[0]), "=r"(r[1]), "=r"(r[2]), "=r"(r[3]) : "r"(addr));
}
__device__ __forceinline__ void mma16816(float* d, const uint32_t* a, uint32_t b0, uint32_t b1) {
    asm volatile("mma.sync.aligned.m16n8k16.row.col.f32.bf16.bf16.f32 "
                 "{%0,%1,%2,%3}, {%4,%5,%6,%7}, {%8,%9}, {%0,%1,%2,%3};"
                 : "+f"(d[0]), "+f"(d[1]), "+f"(d[2]), "+f"(d[3])
                 : "r"(a[0]), "r"(a[1]), "r"(a[2]), "r"(a[3]), "r"(b0), "r"(b1));
}

// ================= bf16x3 HMMA GEMM =================
// C[M,N] = A @ B ; A:[M,Kd] row-major hi/lo, B:[Kd,N] row-major hi/lo, C fp32.
// Block tile 128x128, Kc=64, 256 threads (8 warps of 64x32).
#define BM 128
#define BN 128
#define BK 64
#define A_STR 144   // (BK*2 + 16) bytes, +1 bank/row
#define B_STR 272   // (BN*2 + 16) bytes
#define SA_BYTES (BM * A_STR)          // 18432
#define SB_BYTES (BK * B_STR)          // 17408
#define STAGE_BYTES (2 * SA_BYTES + 2 * SB_BYTES)  // 71680
#define GEMM_SMEM (2 * STAGE_BYTES)                // 143360

__global__ __launch_bounds__(256, 1)
void hmma3_kernel(const __nv_bfloat16* __restrict__ Ah, const __nv_bfloat16* __restrict__ Al,
                  const __nv_bfloat16* __restrict__ Bh, const __nv_bfloat16* __restrict__ Bl,
                  float* __restrict__ C, int N, int Kd, int acc)
{
    extern __shared__ char smem[];
    const uint32_t sb = smem_u32(smem);
    const int tid  = threadIdx.x;
    const int lane = tid & 31;
    const int wid  = tid >> 5;
    const int wr   = wid & 1;     // warp m-row (0..1) -> 64 rows each
    const int wc   = wid >> 1;    // warp n-col (0..3) -> 32 cols each
    const int row0 = blockIdx.x * BM;
    const int col0 = blockIdx.y * BN;
    const int nch  = Kd >> 6;

    float accf[4][4][4];
#pragma unroll
    for (int i = 0; i < 4; i++)
#pragma unroll
        for (int j = 0; j < 4; j++)
#pragma unroll
            for (int q = 0; q < 4; q++) accf[i][j][q] = 0.f;

    // per-thread load coords
    const int ar = tid >> 1;            // A: 2 thr/row, 8x16B per row -> it covers c  (it*2 + (tid&1))? use idx scheme
    // A: 1024 16B chunks (128 rows x 8), 4 iters
    // B: 1024 16B chunks (64 rows x 16), 4 iters

    auto load_stage = [&](int stg, int k0) {
        uint32_t s0 = sb + stg * STAGE_BYTES;
#pragma unroll
        for (int it = 0; it < 4; it++) {
            int idx = it * 256 + tid;
            int r = idx >> 3, c = idx & 7;
            const __nv_bfloat16* gh = Ah + (size_t)(row0 + r) * Kd + k0 + c * 8;
            const __nv_bfloat16* gl = Al + (size_t)(row0 + r) * Kd + k0 + c * 8;
            uint32_t d = s0 + r * A_STR + c * 16;
            cp16(d, gh);
            cp16(d + SA_BYTES, gl);
        }
#pragma unroll
        for (int it = 0; it < 4; it++) {
            int idx = it * 256 + tid;
            int r = idx >> 4, c = idx & 15;
            const __nv_bfloat16* gh = Bh + (size_t)(k0 + r) * N + col0 + c * 8;
            const __nv_bfloat16* gl = Bl + (size_t)(k0 + r) * N + col0 + c * 8;
            uint32_t d = s0 + 2 * SA_BYTES + r * B_STR + c * 16;
            cp16(d, gh);
            cp16(d + SB_BYTES, gl);
        }
        cp_commit();
    };

    load_stage(0, 0);

    // ldmatrix lane addressing (constant parts)
    const int a_row = wr * 64 + (lane & 15);          // + mi*16
    const int a_colb = (lane >> 4) << 4;              // bytes: (lane/16)*8 elems *2
    const int b_row = lane & 15;                      // + k16
    const int b_colb = (wc * 32 + ((lane >> 4) << 3)) * 2;  // + ni16*32 bytes

    for (int ch = 0; ch < nch; ch++) {
        if (ch + 1 < nch) load_stage((ch + 1) & 1, (ch + 1) << 6);
        if (ch + 1 < nch) cp_wait<1>(); else cp_wait<0>();
        __syncthreads();

        uint32_t sA = sb + (ch & 1) * STAGE_BYTES;
        uint32_t sB = sA + 2 * SA_BYTES;

#pragma unroll
        for (int ks = 0; ks < 4; ks++) {
            const int k16 = ks << 4;
            uint32_t Ahf[4][4], Alf[4][4], Bhf[2][4], Blf[2][4];
#pragma unroll
            for (int mi = 0; mi < 4; mi++) {
                uint32_t ad = sA + (a_row + mi * 16) * A_STR + k16 * 2 + a_colb;
                ldsm4(Ahf[mi], ad);
                ldsm4(Alf[mi], ad + SA_BYTES);
            }
#pragma unroll
            for (int nh = 0; nh < 2; nh++) {
                uint32_t bd = sB + (b_row + k16) * B_STR + b_colb + nh * 32;
                ldsm4t(Bhf[nh], bd);
                ldsm4t(Blf[nh], bd + SB_BYTES);
            }
#pragma unroll
            for (int mi = 0; mi < 4; mi++)
#pragma unroll
                for (int ni = 0; ni < 4; ni++) {
                    const int h = ni >> 1, q = (ni & 1) << 1;
                    mma16816(accf[mi][ni], Ahf[mi], Bhf[h][q], Bhf[h][q + 1]);
                    mma16816(accf[mi][ni], Alf[mi], Bhf[h][q], Bhf[h][q + 1]);
                    mma16816(accf[mi][ni], Ahf[mi], Blf[h][q], Blf[h][q + 1]);
                }
        }
        __syncthreads();
    }

    // epilogue
    const int er = row0 + wr * 64 + (lane >> 2);
    const int ec = col0 + wc * 32 + (lane & 3) * 2;
#pragma unroll
    for (int mi = 0; mi < 4; mi++)
#pragma unroll
        for (int ni = 0; ni < 4; ni++) {
            float* p0 = C + (size_t)(er + mi * 16) * N + ec + ni * 8;
            float* p1 = p0 + 8 * N;
            if (acc) {
                float2 o0 = *(float2*)p0, o1 = *(float2*)p1;
                accf[mi][ni][0] += o0.x; accf[mi][ni][1] += o0.y;
                accf[mi][ni][2] += o1.x; accf[mi][ni][3] += o1.y;
            }
            *(float2*)p0 = make_float2(accf[mi][ni][0], accf[mi][ni][1]);
            *(float2*)p1 = make_float2(accf[mi][ni][2], accf[mi][ni][3]);
        }
}

// ================= split fp32 -> bf16 hi/lo =================
__global__ void split_kernel(const float* __restrict__ src,
                             __nv_bfloat16* __restrict__ hi,
                             __nv_bfloat16* __restrict__ lo, int n)
{
    int i = blockIdx.x * 256 + threadIdx.x;
    if (i >= n) return;
    float v = src[i];
    __nv_bfloat16 h = __float2bfloat16_rn(v);
    hi[i] = h;
    lo[i] = __float2bfloat16_rn(v - __bfloat162float(h));
}

// ================= amplitudes -> normalized mix =================
__global__ void mix_kernel(const float* __restrict__ amp)
{
    int e = threadIdx.x;
    if (e >= NE) return;
    float p[KQ];
    float s = 0.f;
#pragma unroll
    for (int k = 0; k < KQ; k++) {
        float a0 = amp[(e * KQ + k) * 2 + 0];
        float a1 = amp[(e * KQ + k) * 2 + 1];
        p[k] = a0 * a0 + a1 * a1;
        s += p[k];
    }
    float inv = 1.f / (s + 1e-8f);
#pragma unroll
    for (int k = 0; k < KQ; k++) g_mix[e * KQ + k] = p[k] * inv;
}

// ================= softmax + top-4 + collapse =================
__global__ void topk_kernel(const float* __restrict__ expert_scale)
{
    int lane = threadIdx.x & 31;
    int warp = threadIdx.x >> 5;
    int t = blockIdx.x * 8 + warp;
    const float* lrow = g_logits + (size_t)t * NE;

    float v[4];
#pragma unroll
    for (int j = 0; j < 4; j++) v[j] = lrow[lane + 32 * j];

    float m = fmaxf(fmaxf(v[0], v[1]), fmaxf(v[2], v[3]));
#pragma unroll
    for (int o = 16; o; o >>= 1) m = fmaxf(m, __shfl_xor_sync(0xffffffffu, m, o));

    float D = 0.f;
#pragma unroll
    for (int j = 0; j < 4; j++) D += expf(v[j] - m);
#pragma unroll
    for (int o = 16; o; o >>= 1) D += __shfl_xor_sync(0xffffffffu, D, o);

    float lv[4] = {v[0], v[1], v[2], v[3]};
    float selv[4];
    int   seli[4];
#pragma unroll
    for (int it = 0; it < 4; it++) {
        float bv = -FLT_MAX;
        int   bi = NE;
#pragma unroll
        for (int j = 0; j < 4; j++) {
            int e = lane + 32 * j;
            if (lv[j] > bv) { bv = lv[j]; bi = e; }
        }
#pragma unroll
        for (int o = 16; o; o >>= 1) {
            float ov = __shfl_xor_sync(0xffffffffu, bv, o);
            int   oi = __shfl_xor_sync(0xffffffffu, bi, o);
            if (ov > bv || (ov == bv && oi < bi)) { bv = ov; bi = oi; }
        }
        selv[it] = bv;
        seli[it] = bi;
        if ((bi & 31) == lane) lv[bi >> 5] = -FLT_MAX;
    }

    float ew[4];
    float S = 0.f;
#pragma unroll
    for (int it = 0; it < 4; it++) { ew[it] = expf(selv[it] - m); S += ew[it]; }
    float denom = S + 1e-8f * D;

    if (lane < KQ) {
        float acc = 0.f;
#pragma unroll
        for (int it = 0; it < 4; it++)
            acc += (ew[it] / denom) * expert_scale[seli[it]] * g_mix[seli[it] * KQ + lane];
        g_wk[t * KQ + lane] = acc;
    }
}

// ================= z = sum_k wk * silu(gate) * up  (writes bf16 hi/lo) =================
__global__ void moe_mix_kernel()
{
    int t = blockIdx.y;
    int i = blockIdx.x * 256 + threadIdx.x;
    __shared__ float w[KQ];
    if (threadIdx.x < KQ) w[threadIdx.x] = g_wk[t * KQ + threadIdx.x];
    __syncthreads();
    float acc = 0.f;
#pragma unroll
    for (int k = 0; k < KQ; k++) {
        size_t off = (size_t)t * KI + k * ID + i;
        float g = g_gate[off];
        float u = g_up[off];
        acc += w[k] * (g / (1.f + expf(-g))) * u;
    }
    size_t zo = (size_t)t * ID + i;
    __nv_bfloat16 h = __float2bfloat16_rn(acc);
    g_zh[zo] = h;
    g_zl[zo] = __float2bfloat16_rn(acc - __bfloat162float(h));
}

// ================= shared expert elementwise (writes bf16 hi/lo) =================
__global__ void silu_mul_kernel()
{
    size_t idx = (size_t)blockIdx.x * 256 + threadIdx.x;
    float g = g_sg[idx];
    float u = g_su[idx];
    float v = (g / (1.f + expf(-g))) * u;
    __nv_bfloat16 h = __float2bfloat16_rn(v);
    g_hh[idx] = h;
    g_hl[idx] = __float2bfloat16_rn(v - __bfloat162float(h));
}

// ================= host side =================
static void gemm3(const void* Ah, const void* Al, const void* Bh, const void* Bl,
                  float* C, int M, int N, int Kd, int acc)
{
    dim3 grid(M / BM, N / BN);
    hmma3_kernel<<<grid, 256, GEMM_SMEM>>>(
        (const __nv_bfloat16*)Ah, (const __nv_bfloat16*)Al,
        (const __nv_bfloat16*)Bh, (const __nv_bfloat16*)Bl, C, N, Kd, acc);
}

extern "C" void kernel_launch(void* const* d_in, const int* in_sizes, int n_in,
                              void* d_out, int out_size)
{
    const float* x             = (const float*)d_in[0];
    const float* w_router      = (const float*)d_in[1];
    const float* w_gate        = (const float*)d_in[2];
    const float* w_up          = (const float*)d_in[3];
    const float* w_down        = (const float*)d_in[4];
    const float* amplitudes    = (const float*)d_in[5];
    const float* expert_scale  = (const float*)d_in[6];
    const float* shared_w_gate = (const float*)d_in[7];
    const float* shared_w_up   = (const float*)d_in[8];
    const float* shared_w_down = (const float*)d_in[9];
    float* out = (float*)d_out;

    cudaFuncSetAttribute(hmma3_kernel, cudaFuncAttributeMaxDynamicSharedMemorySize, GEMM_SMEM);

    void *xh, *xl, *wgh, *wgl, *wuh, *wul, *wdh, *wdl;
    void *sgh, *sgl, *suh, *sul, *sdh, *sdl, *wrh, *wrl;
    void *zh, *zl, *hh, *hl, *pg, *pu, *psg, *psu, *plog;
    cudaGetSymbolAddress(&xh, g_xh);   cudaGetSymbolAddress(&xl, g_xl);
    cudaGetSymbolAddress(&wgh, g_wgh); cudaGetSymbolAddress(&wgl, g_wgl);
    cudaGetSymbolAddress(&wuh, g_wuh); cudaGetSymbolAddress(&wul, g_wul);
    cudaGetSymbolAddress(&wdh, g_wdh); cudaGetSymbolAddress(&wdl, g_wdl);
    cudaGetSymbolAddress(&sgh, g_sgh); cudaGetSymbolAddress(&sgl, g_sgl);
    cudaGetSymbolAddress(&suh, g_suh); cudaGetSymbolAddress(&sul, g_sul);
    cudaGetSymbolAddress(&sdh, g_sdh); cudaGetSymbolAddress(&sdl, g_sdl);
    cudaGetSymbolAddress(&wrh, g_wrh); cudaGetSymbolAddress(&wrl, g_wrl);
    cudaGetSymbolAddress(&zh, g_zh);   cudaGetSymbolAddress(&zl, g_zl);
    cudaGetSymbolAddress(&hh, g_hh);   cudaGetSymbolAddress(&hl, g_hl);
    cudaGetSymbolAddress(&pg, g_gate); cudaGetSymbolAddress(&pu, g_up);
    cudaGetSymbolAddress(&psg, g_sg);  cudaGetSymbolAddress(&psu, g_su);
    cudaGetSymbolAddress(&plog, g_logits);

    // 1. split fp32 inputs into bf16 hi/lo
    split_kernel<<<(T_TOK * HD) / 256, 256>>>(x, (__nv_bfloat16*)xh, (__nv_bfloat16*)xl, T_TOK * HD);
    split_kernel<<<(HD * KI) / 256, 256>>>(w_gate, (__nv_bfloat16*)wgh, (__nv_bfloat16*)wgl, HD * KI);
    split_kernel<<<(HD * KI) / 256, 256>>>(w_up, (__nv_bfloat16*)wuh, (__nv_bfloat16*)wul, HD * KI);
    split_kernel<<<(ID * HD) / 256, 256>>>(w_down, (__nv_bfloat16*)wdh, (__nv_bfloat16*)wdl, ID * HD);
    split_kernel<<<(HD * I2) / 256, 256>>>(shared_w_gate, (__nv_bfloat16*)sgh, (__nv_bfloat16*)sgl, HD * I2);
    split_kernel<<<(HD * I2) / 256, 256>>>(shared_w_up, (__nv_bfloat16*)suh, (__nv_bfloat16*)sul, HD * I2);
    split_kernel<<<(I2 * HD) / 256, 256>>>(shared_w_down, (__nv_bfloat16*)sdh, (__nv_bfloat16*)sdl, I2 * HD);
    split_kernel<<<(HD * NE) / 256, 256>>>(w_router, (__nv_bfloat16*)wrh, (__nv_bfloat16*)wrl, HD * NE);

    // 2. mixing weights
    mix_kernel<<<1, 128>>>(amplitudes);

    // 3. router logits [T,NE]
    gemm3(xh, xl, wrh, wrl, (float*)plog, T_TOK, NE, HD, 0);

    // 4. top-4 + collapse
    topk_kernel<<<T_TOK / 8, 256>>>(expert_scale);

    // 5. gate / up projections [T,KI]
    gemm3(xh, xl, wgh, wgl, (float*)pg, T_TOK, KI, HD, 0);
    gemm3(xh, xl, wuh, wul, (float*)pu, T_TOK, KI, HD, 0);

    // 6. z = sum_k wk * silu(gate) * up  -> bf16 hi/lo
    moe_mix_kernel<<<dim3(ID / 256, T_TOK), 256>>>();

    // 7. down projection: out = z @ w_down
    gemm3(zh, zl, wdh, wdl, out, T_TOK, HD, ID, 0);

    // 8. shared expert
    gemm3(xh, xl, sgh, sgl, (float*)psg, T_TOK, I2, HD, 0);
    gemm3(xh, xl, suh, sul, (float*)psu, T_TOK, I2, HD, 0);
    silu_mul_kernel<<<(T_TOK * I2) / 256, 256>>>();

    // 9. out += h @ shared_w_down
    gemm3(hh, hl, sdh, sdl, out, T_TOK, HD, I2, 1);
}